// round 2
// baseline (speedup 1.0000x reference)
#include <cuda_runtime.h>
#include <cstdint>

#define N_DENSE   13
#define N_FIELDS  26
#define PER_FIELD 100000
#define FEATURE_NUM 2600013   // 26*100000 + 13
#define KDIM 16
#define BATCH 4096

#define WARPS_PER_BLOCK 8
#define THREADS (WARPS_PER_BLOCK * 32)

__global__ __launch_bounds__(THREADS, 4)
void fm_kernel(const float* __restrict__ dense,   // [B, 13]
               const int*   __restrict__ sparse,  // [B, 26]
               const float* __restrict__ w0,      // [1]
               const float* __restrict__ w,       // [FEATURE_NUM, 1]
               const float* __restrict__ V,       // [16, FEATURE_NUM]
               float*       __restrict__ out)     // [B, 1]
{
    const int warp_in_blk = threadIdx.x >> 5;
    const int lane = threadIdx.x & 31;
    const int row  = blockIdx.x * WARPS_PER_BLOCK + warp_in_blk;
    if (row >= BATCH) return;   // never taken (4096 rows, 4096 warps) — warps stay full

    const int k    = lane & 15;     // latent dim handled by this lane
    const int half = lane >> 4;     // 0: even fields, 1: odd fields

    // ---- preload this row's sparse indices; lane j (<26) holds idx_j
    int myidx = 0;
    if (lane < N_FIELDS) {
        myidx = N_DENSE + lane * PER_FIELD + sparse[row * N_FIELDS + lane];
    }
    // lane d (<13) holds dense value d
    float myd = (lane < N_DENSE) ? dense[row * N_DENSE + lane] : 0.f;

    const float* __restrict__ Vk = V + (size_t)k * FEATURE_NUM;

    // ---- sparse second-order gathers: 13 independent LDGs per lane (MLP=13)
    float e = 0.f, sq = 0.f;
    #pragma unroll
    for (int t = 0; t < 13; ++t) {
        const int j = half + 2 * t;                       // converged: all lanes loop 13x
        const int gidx = __shfl_sync(0xffffffffu, myidx, j);
        const float v = __ldg(Vk + gidx);
        e  += v;
        sq += v * v;
    }

    // ---- dense part: ALL lanes execute every shfl (no divergence);
    //      only half==0 accumulates (half-merge below sums the halves).
    #pragma unroll
    for (int d = 0; d < N_DENSE; ++d) {
        const float dd = __shfl_sync(0xffffffffu, myd, d);
        const float vk = __ldg(Vk + d);                   // L1-resident
        if (half == 0) {
            e  += dd * vk;
            sq += (dd * dd) * (vk * vk);
        }
    }

    // merge halves -> every lane has full e[k], sq[k]
    e  += __shfl_xor_sync(0xffffffffu, e, 16);
    sq += __shfl_xor_sync(0xffffffffu, sq, 16);

    // second order: 0.5 * sum_k (e^2 - sq)
    float t2 = e * e - sq;
    #pragma unroll
    for (int s = 8; s >= 1; s >>= 1)
        t2 += __shfl_xor_sync(0xffffffffu, t2, s);

    // ---- first order: sum_j w[idx_j] + sum_d dense_d * w[d]
    float f = 0.f;
    if (lane < N_FIELDS) f  = __ldg(w + myidx);
    if (lane < N_DENSE)  f += myd * __ldg(w + lane);
    #pragma unroll
    for (int s = 16; s >= 1; s >>= 1)
        f += __shfl_xor_sync(0xffffffffu, f, s);

    if (lane == 0) {
        out[row] = w0[0] + f + 0.5f * t2;
    }
}

extern "C" void kernel_launch(void* const* d_in, const int* in_sizes, int n_in,
                              void* d_out, int out_size)
{
    const float* dense  = (const float*)d_in[0];
    const int*   sparse = (const int*)  d_in[1];
    const float* w0     = (const float*)d_in[2];
    const float* w      = (const float*)d_in[3];
    const float* V      = (const float*)d_in[4];
    float* out = (float*)d_out;

    const int blocks = (BATCH + WARPS_PER_BLOCK - 1) / WARPS_PER_BLOCK;
    fm_kernel<<<blocks, THREADS>>>(dense, sparse, w0, w, V, out);
}

// round 3
// speedup vs baseline: 1.0038x; 1.0038x over previous
#include <cuda_runtime.h>
#include <cstdint>

#define N_DENSE   13
#define N_FIELDS  26
#define PER_FIELD 100000
#define FEATURE_NUM 2600013   // 26*100000 + 13
#define BATCH 4096

#define ROWS_PER_BLOCK 4
#define THREADS 256           // 8 warps = 4 rows x 2 sub-warps

__global__ __launch_bounds__(THREADS, 7)
void fm_kernel(const float* __restrict__ dense,   // [B, 13]
               const int*   __restrict__ sparse,  // [B, 26]
               const float* __restrict__ w0,      // [1]
               const float* __restrict__ w,       // [FEATURE_NUM, 1]
               const float* __restrict__ V,       // [16, FEATURE_NUM]
               float*       __restrict__ out)     // [B, 1]
{
    __shared__ float s_e [ROWS_PER_BLOCK][16];
    __shared__ float s_sq[ROWS_PER_BLOCK][16];
    __shared__ float s_f [ROWS_PER_BLOCK];

    const int warp      = threadIdx.x >> 5;
    const int lane      = threadIdx.x & 31;
    const int row_local = warp >> 1;
    const int sub       = warp & 1;          // 0: fields 0-13 + dense, 1: fields 14-25
    const int row       = blockIdx.x * ROWS_PER_BLOCK + row_local;

    const int k    = lane & 15;              // latent dim for this lane
    const int half = lane >> 4;

    // preload the row's 26 global indices (lane j < 26 holds idx_j; both warps redundantly)
    int myidx = 0;
    if (lane < N_FIELDS)
        myidx = N_DENSE + lane * PER_FIELD + sparse[row * N_FIELDS + lane];
    float myd = (lane < N_DENSE) ? dense[row * N_DENSE + lane] : 0.f;

    const float* __restrict__ Vk = V + (size_t)k * FEATURE_NUM;

    float e = 0.f, sq = 0.f;
    if (sub == 0) {
        // fields j = half + 2t, t = 0..6  -> j in 0..13 ; 7 independent LDGs/lane
        #pragma unroll
        for (int t = 0; t < 7; ++t) {
            const int j = half + 2 * t;
            const int g = __shfl_sync(0xffffffffu, myidx, j);
            const float v = __ldg(Vk + g);
            e  += v;
            sq += v * v;
        }
        // dense part (L1-resident coefficients); only half 0 accumulates,
        // all lanes execute every shfl (converged)
        #pragma unroll
        for (int d = 0; d < N_DENSE; ++d) {
            const float dd = __shfl_sync(0xffffffffu, myd, d);
            const float vk = __ldg(Vk + d);
            if (half == 0) {
                e  += dd * vk;
                sq += (dd * dd) * (vk * vk);
            }
        }
    } else {
        // fields j = half + 2t, t = 7..12 -> j in 14..25 ; 6 independent LDGs/lane
        #pragma unroll
        for (int t = 7; t < 13; ++t) {
            const int j = half + 2 * t;
            const int g = __shfl_sync(0xffffffffu, myidx, j);
            const float v = __ldg(Vk + g);
            e  += v;
            sq += v * v;
        }
    }

    // merge halves within warp -> every lane holds partial e[k], sq[k]
    e  += __shfl_xor_sync(0xffffffffu, e, 16);
    sq += __shfl_xor_sync(0xffffffffu, sq, 16);

    // first order partial (split the 26 w-gathers between the two warps)
    float f = 0.f;
    if (sub == 0) {
        if (lane < N_DENSE) f = __ldg(w + myidx) + myd * __ldg(w + lane);
    } else {
        if (lane >= N_DENSE && lane < N_FIELDS) f = __ldg(w + myidx);
    }
    #pragma unroll
    for (int s = 16; s >= 1; s >>= 1)
        f += __shfl_xor_sync(0xffffffffu, f, s);

    // cross-warp combine via smem
    if (sub == 1) {
        if (lane < 16) {
            s_e [row_local][lane] = e;
            s_sq[row_local][lane] = sq;
        }
        if (lane == 0) s_f[row_local] = f;
    }
    __syncthreads();

    if (sub == 0) {
        const float et = e  + s_e [row_local][k];
        const float st = sq + s_sq[row_local][k];
        float t2 = et * et - st;
        #pragma unroll
        for (int s = 8; s >= 1; s >>= 1)
            t2 += __shfl_xor_sync(0xffffffffu, t2, s);
        if (lane == 0)
            out[row] = w0[0] + f + s_f[row_local] + 0.5f * t2;
    }
}

extern "C" void kernel_launch(void* const* d_in, const int* in_sizes, int n_in,
                              void* d_out, int out_size)
{
    const float* dense  = (const float*)d_in[0];
    const int*   sparse = (const int*)  d_in[1];
    const float* w0     = (const float*)d_in[2];
    const float* w      = (const float*)d_in[3];
    const float* V      = (const float*)d_in[4];
    float* out = (float*)d_out;

    const int blocks = BATCH / ROWS_PER_BLOCK;   // 1024
    fm_kernel<<<blocks, THREADS>>>(dense, sparse, w0, w, V, out);
}